// round 1
// baseline (speedup 1.0000x reference)
#include <cuda_runtime.h>
#include <math.h>

#define NN 50000
#define EE 800000
#define IN_DIM 128
#define EMB 64
#define HDIM 256
#define RR 12
#define BB 8
#define NHEADS 4
#define NGENE 20000
#define NPATH 2000
#define IN1 192

// ---------------- static scratch (allowed: __device__ globals) ----------------
__device__ float g_x0[(size_t)NN * IN1];            // layer-1 input  [N,192]
__device__ float g_h1[(size_t)NN * HDIM];           // layer-1 output [N,256]
__device__ float g_h2[(size_t)NN * HDIM];           // layer-2 output [N,256]
__device__ float g_aggR[(size_t)NN * RR * HDIM];    // per-(node,rel) sums (max K=256)
__device__ float g_aggB[(size_t)NN * BB * HDIM];    // per-(node,basis) compressed
__device__ int   g_cnt[NN * RR];
__device__ float g_invc[NN * RR];

// ---------------- small prep kernels ----------------
__global__ void k_build_x0(const float* __restrict__ x) {
    int i = blockIdx.x * blockDim.x + threadIdx.x;
    if (i >= NN * IN1) return;
    int n = i / IN1, c = i - n * IN1;
    g_x0[i] = (c < IN_DIM) ? x[(size_t)n * IN_DIM + c] : 0.0f;
}

__global__ void k_add_emb(const int* __restrict__ idx, const float* __restrict__ emb, int cnt) {
    int t = blockIdx.x * blockDim.x + threadIdx.x;
    if (t >= cnt * EMB) return;
    int g = t / EMB, j = t - g * EMB;
    atomicAdd(&g_x0[(size_t)idx[g] * IN1 + IN_DIM + j], emb[t]);
}

__global__ void k_zero_cnt() {
    int i = blockIdx.x * blockDim.x + threadIdx.x;
    if (i < NN * RR) g_cnt[i] = 0;
}

__global__ void k_count(const int* __restrict__ ei, const int* __restrict__ et) {
    int e = blockIdx.x * blockDim.x + threadIdx.x;
    if (e >= EE) return;
    int dst = ei[EE + e];
    atomicAdd(&g_cnt[dst * RR + et[e]], 1);
}

__global__ void k_invc() {
    int i = blockIdx.x * blockDim.x + threadIdx.x;
    if (i >= NN * RR) return;
    int c = g_cnt[i];
    g_invc[i] = 1.0f / (c > 0 ? (float)c : 1.0f);
}

__global__ void k_zero_agg(long long n4) {   // zero g_aggR, float4 granularity
    long long i = (long long)blockIdx.x * blockDim.x + threadIdx.x;
    if (i < n4) reinterpret_cast<float4*>(g_aggR)[i] = make_float4(0.f, 0.f, 0.f, 0.f);
}

// ---------------- scatter: aggR[dst,rel,:] += x[src,:] ----------------
template <int K, int LAYER>
__global__ void k_scatter(const int* __restrict__ ei, const int* __restrict__ et) {
    long long idx = (long long)blockIdx.x * blockDim.x + threadIdx.x;
    if (idx >= (long long)EE * K) return;
    int e = (int)(idx / K);
    int i = (int)(idx - (long long)e * K);
    int src = ei[e];
    int dst = ei[EE + e];
    int r   = et[e];
    const float* xin = (LAYER == 1) ? g_x0 : g_h1;
    atomicAdd(&g_aggR[((size_t)dst * RR + r) * K + i], xin[(size_t)src * K + i]);
}

// ---------------- compress: aggB[n,b,:] = sum_r comp[r,b]*invc[n,r]*aggR[n,r,:] ----------------
template <int K>
__global__ void k_compress(const float* __restrict__ comp) {
    __shared__ float sc[RR * BB];
    int tid = threadIdx.x;
    if (tid < RR * BB) sc[tid] = comp[tid];
    __syncthreads();

    long long idx = (long long)blockIdx.x * blockDim.x + tid;
    if (idx >= (long long)NN * K) return;
    int n = (int)(idx / K);
    int i = (int)(idx - (long long)n * K);

    float a[RR];
#pragma unroll
    for (int r = 0; r < RR; r++)
        a[r] = g_aggR[((size_t)n * RR + r) * K + i] * g_invc[n * RR + r];

#pragma unroll
    for (int b = 0; b < BB; b++) {
        float acc = 0.f;
#pragma unroll
        for (int r = 0; r < RR; r++) acc = fmaf(sc[r * BB + b], a[r], acc);
        g_aggB[((size_t)n * BB + b) * K + i] = acc;
    }
}

// ---------------- fused GEMM + bias + head-softmax attention ----------------
// h[n,:] = softmax_heads( [aggB[n] | xin[n]] @ [basis; root] + bias ) scaling
// Tile: BM=64 rows x BN=256 cols (all of H), BK=16, 256 threads, 8x8 microtile.
// Thread cols: {tx*4 .. tx*4+3} and {128+tx*4 .. 128+tx*4+3}  (conflict-free LDS.128)
template <int KIN, int LAYER>
__global__ void __launch_bounds__(256, 2)
k_gemm_attn(const float* __restrict__ basis, const float* __restrict__ root,
            const float* __restrict__ bias,  const float* __restrict__ att) {
    constexpr int KB   = BB * KIN;
    constexpr int KTOT = KB + KIN;
    constexpr int BM = 64, BN = 256, BK = 16;
    constexpr int T = KTOT / BK;
    static_assert(KB % BK == 0 && KTOT % BK == 0, "tile alignment");

    __shared__ float As[2][BK][BM];
    __shared__ float Bs[2][BK][BN];

    const float* xin  = (LAYER == 1) ? g_x0 : g_h1;
    float*       hout = (LAYER == 1) ? g_h1 : g_h2;

    const int tid = threadIdx.x;
    const int tx = tid & 31;
    const int ty = tid >> 5;
    const int bm = blockIdx.x * BM;

    const int arow = tid >> 2;           // 0..63
    const int acol = (tid & 3) << 2;     // 0,4,8,12
    const int brow = tid >> 4;           // 0..15
    const int bcol = (tid & 15) << 4;    // 0..240

    float acc[8][8];
#pragma unroll
    for (int i = 0; i < 8; i++)
#pragma unroll
        for (int j = 0; j < 8; j++) acc[i][j] = 0.f;

    float4 aReg;
    float4 bReg[4];

    auto gload = [&](int k0) {
        int n  = bm + arow;
        int ka = k0 + acol;
        if (n < NN) {
            const float* p = (ka < KB) ? (g_aggB + (size_t)n * KB + ka)
                                       : (xin + (size_t)n * KIN + (ka - KB));
            aReg = *reinterpret_cast<const float4*>(p);
        } else {
            aReg = make_float4(0.f, 0.f, 0.f, 0.f);
        }
        int kb = k0 + brow;
        const float* bp = (kb < KB) ? (basis + (size_t)kb * BN + bcol)
                                    : (root + (size_t)(kb - KB) * BN + bcol);
#pragma unroll
        for (int j = 0; j < 4; j++)
            bReg[j] = *reinterpret_cast<const float4*>(bp + j * 4);
    };
    auto sstore = [&](int buf) {
        As[buf][acol + 0][arow] = aReg.x;
        As[buf][acol + 1][arow] = aReg.y;
        As[buf][acol + 2][arow] = aReg.z;
        As[buf][acol + 3][arow] = aReg.w;
#pragma unroll
        for (int j = 0; j < 4; j++)
            *reinterpret_cast<float4*>(&Bs[buf][brow][bcol + j * 4]) = bReg[j];
    };

    gload(0);
    sstore(0);
    __syncthreads();

    for (int t = 0; t < T; t++) {
        int cur = t & 1;
        if (t + 1 < T) gload((t + 1) * BK);
#pragma unroll
        for (int kk = 0; kk < BK; kk++) {
            float4 av0 = *reinterpret_cast<const float4*>(&As[cur][kk][ty * 8]);
            float4 av1 = *reinterpret_cast<const float4*>(&As[cur][kk][ty * 8 + 4]);
            float4 bv0 = *reinterpret_cast<const float4*>(&Bs[cur][kk][tx * 4]);
            float4 bv1 = *reinterpret_cast<const float4*>(&Bs[cur][kk][128 + tx * 4]);
            float a[8] = {av0.x, av0.y, av0.z, av0.w, av1.x, av1.y, av1.z, av1.w};
            float b[8] = {bv0.x, bv0.y, bv0.z, bv0.w, bv1.x, bv1.y, bv1.z, bv1.w};
#pragma unroll
            for (int i = 0; i < 8; i++)
#pragma unroll
                for (int j = 0; j < 8; j++)
                    acc[i][j] = fmaf(a[i], b[j], acc[i][j]);
        }
        if (t + 1 < T) sstore(cur ^ 1);
        __syncthreads();
    }

    // bias
    float bval[8];
#pragma unroll
    for (int j = 0; j < 4; j++) {
        bval[j]     = bias[tx * 4 + j];
        bval[4 + j] = bias[128 + tx * 4 + j];
    }
#pragma unroll
    for (int i = 0; i < 8; i++)
#pragma unroll
        for (int j = 0; j < 8; j++) acc[i][j] += bval[j];

    // attention: cols tx*4.. belong to head hA = tx>>4 (0/1); cols 128+tx*4.. to head hA+2
    const int hA = tx >> 4;
    const int jbase = (tx & 15) * 4;
    float attA[4], attB[4];
#pragma unroll
    for (int c = 0; c < 4; c++) {
        attA[c] = att[hA * 64 + jbase + c];
        attB[c] = att[(hA + 2) * 64 + jbase + c];
    }

#pragma unroll
    for (int r = 0; r < 8; r++) {
        float sA = acc[r][0] * attA[0] + acc[r][1] * attA[1] +
                   acc[r][2] * attA[2] + acc[r][3] * attA[3];
        float sB = acc[r][4] * attB[0] + acc[r][5] * attB[1] +
                   acc[r][6] * attB[2] + acc[r][7] * attB[3];
#pragma unroll
        for (int off = 1; off < 16; off <<= 1) {
            sA += __shfl_xor_sync(0xffffffffu, sA, off);
            sB += __shfl_xor_sync(0xffffffffu, sB, off);
        }
        // exchange with the other 16-lane half to collect all 4 head scores
        float oA = __shfl_xor_sync(0xffffffffu, sA, 16);
        float oB = __shfl_xor_sync(0xffffffffu, sB, 16);
        float m = fmaxf(fmaxf(sA, oA), fmaxf(sB, oB));
        float eA = expf(sA - m), eB = expf(sB - m);
        float eoA = expf(oA - m), eoB = expf(oB - m);
        float inv = 1.f / (eA + eB + eoA + eoB);
        float alA = eA * inv, alB = eB * inv;
        int n = bm + ty * 8 + r;
        if (n < NN) {
            float4 o0 = make_float4(acc[r][0] * alA, acc[r][1] * alA,
                                    acc[r][2] * alA, acc[r][3] * alA);
            float4 o1 = make_float4(acc[r][4] * alB, acc[r][5] * alB,
                                    acc[r][6] * alB, acc[r][7] * alB);
            *reinterpret_cast<float4*>(&hout[(size_t)n * HDIM + tx * 4]) = o0;
            *reinterpret_cast<float4*>(&hout[(size_t)n * HDIM + 128 + tx * 4]) = o1;
        }
    }
}

// ---------------- final prediction: out = h2 @ pred_w + pred_b ----------------
__global__ void k_pred(const float* __restrict__ pw, const float* __restrict__ pb,
                       float* __restrict__ out) {
    __shared__ float wt[12 * HDIM];   // transposed: wt[j*256+c]
    int tid = threadIdx.x;
    for (int i = tid; i < HDIM * 12; i += blockDim.x) {
        int c = i / 12, j = i - c * 12;
        wt[j * HDIM + c] = pw[i];
    }
    __syncthreads();
    int warp = tid >> 5, lane = tid & 31;
    int n = blockIdx.x * 8 + warp;
    if (n >= NN) return;
    float acc[12];
#pragma unroll
    for (int j = 0; j < 12; j++) acc[j] = 0.f;
#pragma unroll
    for (int c0 = 0; c0 < 8; c0++) {
        int c = c0 * 32 + lane;
        float v = g_h2[(size_t)n * HDIM + c];
#pragma unroll
        for (int j = 0; j < 12; j++) acc[j] = fmaf(v, wt[j * HDIM + c], acc[j]);
    }
#pragma unroll
    for (int j = 0; j < 12; j++) {
#pragma unroll
        for (int off = 16; off; off >>= 1)
            acc[j] += __shfl_xor_sync(0xffffffffu, acc[j], off);
    }
    if (lane == 0) {
#pragma unroll
        for (int j = 0; j < 12; j++) out[(size_t)n * 12 + j] = acc[j] + pb[j];
    }
}

// ---------------- launch ----------------
extern "C" void kernel_launch(void* const* d_in, const int* in_sizes, int n_in,
                              void* d_out, int out_size) {
    const float* x      = (const float*)d_in[0];
    const int*   ei     = (const int*)d_in[1];
    const int*   et     = (const int*)d_in[2];
    const int*   gidx   = (const int*)d_in[3];
    const int*   pidx   = (const int*)d_in[4];
    const float* gemb   = (const float*)d_in[5];
    const float* pemb   = (const float*)d_in[6];
    const float* comp1  = (const float*)d_in[7];
    const float* basis1 = (const float*)d_in[8];
    const float* root1  = (const float*)d_in[9];
    const float* bias1  = (const float*)d_in[10];
    const float* att1   = (const float*)d_in[11];
    const float* comp2  = (const float*)d_in[12];
    const float* basis2 = (const float*)d_in[13];
    const float* root2  = (const float*)d_in[14];
    const float* bias2  = (const float*)d_in[15];
    const float* att2   = (const float*)d_in[16];
    const float* predw  = (const float*)d_in[17];
    const float* predb  = (const float*)d_in[18];
    float* out = (float*)d_out;

    const int TPB = 256;

    // input features + embeddings
    k_build_x0<<<(NN * IN1 + TPB - 1) / TPB, TPB>>>(x);
    k_add_emb<<<(NGENE * EMB + TPB - 1) / TPB, TPB>>>(gidx, gemb, NGENE);
    k_add_emb<<<(NPATH * EMB + TPB - 1) / TPB, TPB>>>(pidx, pemb, NPATH);

    // per-(node,rel) edge counts (same for both layers)
    k_zero_cnt<<<(NN * RR + TPB - 1) / TPB, TPB>>>();
    k_count<<<(EE + TPB - 1) / TPB, TPB>>>(ei, et);
    k_invc<<<(NN * RR + TPB - 1) / TPB, TPB>>>();

    // ---- layer 1 (K = 192) ----
    {
        long long n4 = (long long)NN * RR * IN1 / 4;
        k_zero_agg<<<(unsigned)((n4 + TPB - 1) / TPB), TPB>>>(n4);
        long long tw = (long long)EE * IN1;
        k_scatter<IN1, 1><<<(unsigned)((tw + TPB - 1) / TPB), TPB>>>(ei, et);
        long long cw = (long long)NN * IN1;
        k_compress<IN1><<<(unsigned)((cw + TPB - 1) / TPB), TPB>>>(comp1);
        k_gemm_attn<IN1, 1><<<(NN + 63) / 64, TPB>>>(basis1, root1, bias1, att1);
    }
    // ---- layer 2 (K = 256) ----
    {
        long long n4 = (long long)NN * RR * HDIM / 4;
        k_zero_agg<<<(unsigned)((n4 + TPB - 1) / TPB), TPB>>>(n4);
        long long tw = (long long)EE * HDIM;
        k_scatter<HDIM, 2><<<(unsigned)((tw + TPB - 1) / TPB), TPB>>>(ei, et);
        long long cw = (long long)NN * HDIM;
        k_compress<HDIM><<<(unsigned)((cw + TPB - 1) / TPB), TPB>>>(comp2);
        k_gemm_attn<HDIM, 2><<<(NN + 63) / 64, TPB>>>(basis2, root2, bias2, att2);
    }

    // prediction head
    k_pred<<<(NN + 7) / 8, TPB>>>(predw, predb, out);
}

// round 3
// speedup vs baseline: 1.2424x; 1.2424x over previous
#include <cuda_runtime.h>
#include <math.h>
#include <stdint.h>

#define NN 50000
#define EE 800000
#define IN_DIM 128
#define EMB 64
#define HDIM 256
#define RR 12
#define BB 8
#define NHEADS 4
#define NGENE 20000
#define NPATH 2000
#define IN1 192

// ---------------- static scratch ----------------
__device__ float g_x0[(size_t)NN * IN1];
__device__ float g_h1[(size_t)NN * HDIM];
__device__ float g_h2[(size_t)NN * HDIM];
__device__ float g_aggR[(size_t)NN * RR * HDIM];
__device__ float g_aggB[(size_t)NN * BB * HDIM];
__device__ int   g_cnt[NN * RR];
__device__ float g_invc[NN * RR];

// ---------------- helpers ----------------
__device__ __forceinline__ uint32_t smem_u32(const void* p) {
    uint32_t a;
    asm("{ .reg .u64 t; cvta.to.shared.u64 t, %1; cvt.u32.u64 %0, t; }" : "=r"(a) : "l"(p));
    return a;
}
__device__ __forceinline__ uint32_t f2tf32(float f) {
    uint32_t r; asm("cvt.rna.tf32.f32 %0, %1;" : "=r"(r) : "f"(f)); return r;
}
__device__ __forceinline__ void split_tf32(float f, uint32_t& hi, uint32_t& lo) {
    hi = f2tf32(f);
    lo = f2tf32(f - __uint_as_float(hi));
}
__device__ __forceinline__ void mma8(float* d, const uint32_t* a, const uint32_t* b) {
    asm volatile(
        "mma.sync.aligned.m16n8k8.row.col.f32.tf32.tf32.f32 "
        "{%0,%1,%2,%3}, {%4,%5,%6,%7}, {%8,%9}, {%0,%1,%2,%3};"
        : "+f"(d[0]), "+f"(d[1]), "+f"(d[2]), "+f"(d[3])
        : "r"(a[0]), "r"(a[1]), "r"(a[2]), "r"(a[3]), "r"(b[0]), "r"(b[1]));
}
__device__ __forceinline__ void cp16(uint32_t dst, const float* src) {
    asm volatile("cp.async.cg.shared.global [%0], [%1], 16;" :: "r"(dst), "l"(src));
}

// ---------------- prep kernels ----------------
__global__ void k_build_x0_zero(const float* __restrict__ x) {
    int i = blockIdx.x * blockDim.x + threadIdx.x;
    if (i < NN * RR) g_cnt[i] = 0;
    if (i >= NN * IN1) return;
    int n = i / IN1, c = i - n * IN1;
    g_x0[i] = (c < IN_DIM) ? x[(size_t)n * IN_DIM + c] : 0.0f;
}

__global__ void k_add_emb(const int* __restrict__ idx, const float* __restrict__ emb, int cnt) {
    int t = blockIdx.x * blockDim.x + threadIdx.x;
    if (t >= cnt * EMB) return;
    int g = t / EMB, j = t - g * EMB;
    atomicAdd(&g_x0[(size_t)idx[g] * IN1 + IN_DIM + j], emb[t]);
}

__global__ void k_count(const int* __restrict__ ei, const int* __restrict__ et) {
    int e = blockIdx.x * blockDim.x + threadIdx.x;
    if (e >= EE) return;
    int dst = ei[EE + e];
    atomicAdd(&g_cnt[dst * RR + et[e]], 1);
}

__global__ void k_invc_zero1(long long n4) {
    long long i = (long long)blockIdx.x * blockDim.x + threadIdx.x;
    if (i < NN * RR) {
        int c = g_cnt[i];
        g_invc[i] = 1.0f / (c > 0 ? (float)c : 1.0f);
    }
    if (i < n4) reinterpret_cast<float4*>(g_aggR)[i] = make_float4(0.f, 0.f, 0.f, 0.f);
}

__global__ void k_zero_agg(long long n4) {
    long long i = (long long)blockIdx.x * blockDim.x + threadIdx.x;
    if (i < n4) reinterpret_cast<float4*>(g_aggR)[i] = make_float4(0.f, 0.f, 0.f, 0.f);
}

// ---------------- scatter ----------------
template <int K, int LAYER>
__global__ void k_scatter(const int* __restrict__ ei, const int* __restrict__ et) {
    long long idx = (long long)blockIdx.x * blockDim.x + threadIdx.x;
    if (idx >= (long long)EE * K) return;
    int e = (int)(idx / K);
    int i = (int)(idx - (long long)e * K);
    int src = ei[e];
    int dst = ei[EE + e];
    int r   = et[e];
    const float* xin = (LAYER == 1) ? g_x0 : g_h1;
    atomicAdd(&g_aggR[((size_t)dst * RR + r) * K + i], xin[(size_t)src * K + i]);
}

// ---------------- compress ----------------
template <int K>
__global__ void k_compress(const float* __restrict__ comp) {
    __shared__ float sc[RR * BB];
    int tid = threadIdx.x;
    if (tid < RR * BB) sc[tid] = comp[tid];
    __syncthreads();

    long long idx = (long long)blockIdx.x * blockDim.x + tid;
    if (idx >= (long long)NN * K) return;
    int n = (int)(idx / K);
    int i = (int)(idx - (long long)n * K);

    float a[RR];
#pragma unroll
    for (int r = 0; r < RR; r++)
        a[r] = g_aggR[((size_t)n * RR + r) * K + i] * g_invc[n * RR + r];

#pragma unroll
    for (int b = 0; b < BB; b++) {
        float acc = 0.f;
#pragma unroll
        for (int r = 0; r < RR; r++) acc = fmaf(sc[r * BB + b], a[r], acc);
        g_aggB[((size_t)n * BB + b) * K + i] = acc;
    }
}

// ---------------- tensor-core GEMM via mma.sync (3xTF32) + bias + head-softmax ----------------
// CTA: 128 rows x 256 cols.  8 warps (2 x 4), warp tile 64x64.  BK=16, cp.async double buffer.
// smem floats: As[2][128][20] @0, Bs[2][16][264] @5120, bias @13568, att @13824,
//              sc[128][4] @14080, al[128][4] @14592. total 15104 floats = 60416 B.
#define GEMM_SMEM_FLOATS 15104
#define GEMM_SMEM_BYTES  (GEMM_SMEM_FLOATS * 4)

template <int KIN, int LAYER>
__global__ void __launch_bounds__(256, 1)
k_gemm_mma(const float* __restrict__ basis, const float* __restrict__ root,
           const float* __restrict__ bias,  const float* __restrict__ att) {
    constexpr int KB   = BB * KIN;
    constexpr int KTOT = 9 * KIN;
    constexpr int T    = KTOT / 16;

    extern __shared__ float sm[];
    float* As     = sm;            // [2][128][20]
    float* Bs     = sm + 5120;     // [2][16][264]
    float* s_bias = sm + 13568;
    float* s_att  = sm + 13824;
    float* s_sc   = sm + 14080;    // [128][4]
    float* s_al   = sm + 14592;    // [128][4]

    const uint32_t smbase = smem_u32(sm);
    const int tid  = threadIdx.x;
    const int lane = tid & 31;
    const int wid  = tid >> 5;
    const int wm   = wid >> 2;     // 0..1
    const int wn   = wid & 3;      // 0..3 (== head)
    const int m0   = blockIdx.x * 128;

    const float* xin  = (LAYER == 1) ? g_x0 : g_h1;
    float*       hout = (LAYER == 1) ? g_h1 : g_h2;

    s_bias[tid] = bias[tid];
    s_att[tid]  = att[tid];

    float acc[4][8][4];
#pragma unroll
    for (int a = 0; a < 4; a++)
#pragma unroll
        for (int b = 0; b < 8; b++)
#pragma unroll
            for (int c = 0; c < 4; c++) acc[a][b][c] = 0.f;

    auto issueA = [&](int t) {
#pragma unroll
        for (int i = 0; i < 2; ++i) {
            int id = tid + i * 256;
            int m = id >> 2, k4 = (id & 3) << 2;
            int row = m0 + m;
            int kc = t * 16 + k4;
            uint32_t dst = smbase + (((t & 1) * 2560 + m * 20 + k4) << 2);
            if (row < NN) {
                const float* src = (kc < KB) ? (g_aggB + (size_t)row * KB + kc)
                                             : (xin + (size_t)row * KIN + (kc - KB));
                cp16(dst, src);
            } else {
                asm volatile("st.shared.v4.b32 [%0], {%1,%1,%1,%1};" :: "r"(dst), "r"(0) : "memory");
            }
        }
    };
    auto issueB = [&](int t) {
#pragma unroll
        for (int i = 0; i < 4; ++i) {
            int id = tid + i * 256;
            int k = id >> 6, n4 = (id & 63) << 2;
            int kk = t * 16 + k;
            const float* src = (kk < KB) ? (basis + (size_t)kk * 256 + n4)
                                         : (root + (size_t)(kk - KB) * 256 + n4);
            uint32_t dst = smbase + ((5120 + (t & 1) * 4224 + k * 264 + n4) << 2);
            cp16(dst, src);
        }
    };

    issueA(0); issueB(0);
    asm volatile("cp.async.commit_group;" ::: "memory");

    for (int t = 0; t < T; ++t) {
        asm volatile("cp.async.wait_group 0;" ::: "memory");
        __syncthreads();
        if (t + 1 < T) {
            issueA(t + 1); issueB(t + 1);
            asm volatile("cp.async.commit_group;" ::: "memory");
        }
        const float* Ac = As + (t & 1) * 2560;
        const float* Bc = Bs + (t & 1) * 4224;
#pragma unroll
        for (int kk0 = 0; kk0 < 16; kk0 += 8) {
            uint32_t ah[4][4], al_[4][4];
#pragma unroll
            for (int mi = 0; mi < 4; ++mi) {
                int mr = wm * 64 + mi * 16 + (lane >> 2);
                int kc0 = kk0 + (lane & 3);
                float f0 = Ac[mr * 20 + kc0];
                float f1 = Ac[(mr + 8) * 20 + kc0];
                float f2 = Ac[mr * 20 + kc0 + 4];
                float f3 = Ac[(mr + 8) * 20 + kc0 + 4];
                split_tf32(f0, ah[mi][0], al_[mi][0]);
                split_tf32(f1, ah[mi][1], al_[mi][1]);
                split_tf32(f2, ah[mi][2], al_[mi][2]);
                split_tf32(f3, ah[mi][3], al_[mi][3]);
            }
#pragma unroll
            for (int ni = 0; ni < 8; ++ni) {
                int nc = wn * 64 + ni * 8 + (lane >> 2);
                float g0 = Bc[(kk0 + (lane & 3)) * 264 + nc];
                float g1 = Bc[(kk0 + (lane & 3) + 4) * 264 + nc];
                uint32_t bh[2], bl[2];
                split_tf32(g0, bh[0], bl[0]);
                split_tf32(g1, bh[1], bl[1]);
#pragma unroll
                for (int mi = 0; mi < 4; ++mi) {
                    mma8(acc[mi][ni], ah[mi], bh);
                    mma8(acc[mi][ni], ah[mi], bl);
                    mma8(acc[mi][ni], al_[mi], bh);
                }
            }
        }
    }

    // ---- bias + head scores (warp tile == one full head) ----
    float sc[8];
#pragma unroll
    for (int i = 0; i < 8; ++i) sc[i] = 0.f;
#pragma unroll
    for (int mi = 0; mi < 4; ++mi)
#pragma unroll
        for (int ni = 0; ni < 8; ++ni) {
            int colb = wn * 64 + ni * 8 + (lane & 3) * 2;
#pragma unroll
            for (int r = 0; r < 4; ++r) {
                int col = colb + (r & 1);
                acc[mi][ni][r] += s_bias[col];
                sc[mi * 2 + (r >> 1)] = fmaf(acc[mi][ni][r], s_att[col], sc[mi * 2 + (r >> 1)]);
            }
        }
#pragma unroll
    for (int i = 0; i < 8; ++i) {
        sc[i] += __shfl_xor_sync(0xffffffffu, sc[i], 1);
        sc[i] += __shfl_xor_sync(0xffffffffu, sc[i], 2);
    }
    if ((lane & 3) == 0) {
#pragma unroll
        for (int mi = 0; mi < 4; ++mi) {
            int r0 = wm * 64 + mi * 16 + (lane >> 2);
            s_sc[r0 * 4 + wn]       = sc[mi * 2];
            s_sc[(r0 + 8) * 4 + wn] = sc[mi * 2 + 1];
        }
    }
    __syncthreads();
    if (tid < 128) {
        float v0 = s_sc[tid * 4], v1 = s_sc[tid * 4 + 1];
        float v2 = s_sc[tid * 4 + 2], v3 = s_sc[tid * 4 + 3];
        float mx = fmaxf(fmaxf(v0, v1), fmaxf(v2, v3));
        float e0 = expf(v0 - mx), e1 = expf(v1 - mx), e2 = expf(v2 - mx), e3 = expf(v3 - mx);
        float inv = 1.f / (e0 + e1 + e2 + e3);
        s_al[tid * 4]     = e0 * inv;
        s_al[tid * 4 + 1] = e1 * inv;
        s_al[tid * 4 + 2] = e2 * inv;
        s_al[tid * 4 + 3] = e3 * inv;
    }
    __syncthreads();

    // ---- scaled store ----
#pragma unroll
    for (int mi = 0; mi < 4; ++mi) {
        int lr0 = wm * 64 + mi * 16 + (lane >> 2);
        int rowA = m0 + lr0, rowB = rowA + 8;
        float aA = s_al[lr0 * 4 + wn];
        float aB = s_al[(lr0 + 8) * 4 + wn];
#pragma unroll
        for (int ni = 0; ni < 8; ++ni) {
            int col = wn * 64 + ni * 8 + (lane & 3) * 2;
            if (rowA < NN) {
                float2 o = make_float2(acc[mi][ni][0] * aA, acc[mi][ni][1] * aA);
                *reinterpret_cast<float2*>(&hout[(size_t)rowA * HDIM + col]) = o;
            }
            if (rowB < NN) {
                float2 o = make_float2(acc[mi][ni][2] * aB, acc[mi][ni][3] * aB);
                *reinterpret_cast<float2*>(&hout[(size_t)rowB * HDIM + col]) = o;
            }
        }
    }
}

// ---------------- final prediction ----------------
__global__ void k_pred(const float* __restrict__ pw, const float* __restrict__ pb,
                       float* __restrict__ out) {
    __shared__ float wt[12 * HDIM];
    int tid = threadIdx.x;
    for (int i = tid; i < HDIM * 12; i += blockDim.x) {
        int c = i / 12, j = i - c * 12;
        wt[j * HDIM + c] = pw[i];
    }
    __syncthreads();
    int warp = tid >> 5, lane = tid & 31;
    int n = blockIdx.x * 8 + warp;
    if (n >= NN) return;
    float acc[12];
#pragma unroll
    for (int j = 0; j < 12; j++) acc[j] = 0.f;
#pragma unroll
    for (int c0 = 0; c0 < 8; c0++) {
        int c = c0 * 32 + lane;
        float v = g_h2[(size_t)n * HDIM + c];
#pragma unroll
        for (int j = 0; j < 12; j++) acc[j] = fmaf(v, wt[j * HDIM + c], acc[j]);
    }
#pragma unroll
    for (int j = 0; j < 12; j++) {
#pragma unroll
        for (int off = 16; off; off >>= 1)
            acc[j] += __shfl_xor_sync(0xffffffffu, acc[j], off);
    }
    if (lane == 0) {
#pragma unroll
        for (int j = 0; j < 12; j++) out[(size_t)n * 12 + j] = acc[j] + pb[j];
    }
}

// ---------------- launch ----------------
extern "C" void kernel_launch(void* const* d_in, const int* in_sizes, int n_in,
                              void* d_out, int out_size) {
    const float* x      = (const float*)d_in[0];
    const int*   ei     = (const int*)d_in[1];
    const int*   et     = (const int*)d_in[2];
    const int*   gidx   = (const int*)d_in[3];
    const int*   pidx   = (const int*)d_in[4];
    const float* gemb   = (const float*)d_in[5];
    const float* pemb   = (const float*)d_in[6];
    const float* comp1  = (const float*)d_in[7];
    const float* basis1 = (const float*)d_in[8];
    const float* root1  = (const float*)d_in[9];
    const float* bias1  = (const float*)d_in[10];
    const float* att1   = (const float*)d_in[11];
    const float* comp2  = (const float*)d_in[12];
    const float* basis2 = (const float*)d_in[13];
    const float* root2  = (const float*)d_in[14];
    const float* bias2  = (const float*)d_in[15];
    const float* att2   = (const float*)d_in[16];
    const float* predw  = (const float*)d_in[17];
    const float* predb  = (const float*)d_in[18];
    float* out = (float*)d_out;

    const int TPB = 256;

    cudaFuncSetAttribute(k_gemm_mma<IN1, 1>,  cudaFuncAttributeMaxDynamicSharedMemorySize, GEMM_SMEM_BYTES);
    cudaFuncSetAttribute(k_gemm_mma<HDIM, 2>, cudaFuncAttributeMaxDynamicSharedMemorySize, GEMM_SMEM_BYTES);

    // features + zero counts
    k_build_x0_zero<<<(NN * IN1 + TPB - 1) / TPB, TPB>>>(x);
    k_add_emb<<<(NGENE * EMB + TPB - 1) / TPB, TPB>>>(gidx, gemb, NGENE);
    k_add_emb<<<(NPATH * EMB + TPB - 1) / TPB, TPB>>>(pidx, pemb, NPATH);
    k_count<<<(EE + TPB - 1) / TPB, TPB>>>(ei, et);
    {
        long long n4 = (long long)NN * RR * IN1 / 4;
        k_invc_zero1<<<(unsigned)((n4 + TPB - 1) / TPB), TPB>>>(n4);
    }
    // ---- layer 1 ----
    {
        long long tw = (long long)EE * IN1;
        k_scatter<IN1, 1><<<(unsigned)((tw + TPB - 1) / TPB), TPB>>>(ei, et);
        long long cw = (long long)NN * IN1;
        k_compress<IN1><<<(unsigned)((cw + TPB - 1) / TPB), TPB>>>(comp1);
        k_gemm_mma<IN1, 1><<<(NN + 127) / 128, 256, GEMM_SMEM_BYTES>>>(basis1, root1, bias1, att1);
    }
    // ---- layer 2 ----
    {
        long long n4 = (long long)NN * RR * HDIM / 4;
        k_zero_agg<<<(unsigned)((n4 + TPB - 1) / TPB), TPB>>>(n4);
        long long tw = (long long)EE * HDIM;
        k_scatter<HDIM, 2><<<(unsigned)((tw + TPB - 1) / TPB), TPB>>>(ei, et);
        long long cw = (long long)NN * HDIM;
        k_compress<HDIM><<<(unsigned)((cw + TPB - 1) / TPB), TPB>>>(comp2);
        k_gemm_mma<HDIM, 2><<<(NN + 127) / 128, 256, GEMM_SMEM_BYTES>>>(basis2, root2, bias2, att2);
    }
    // prediction head
    k_pred<<<(NN + 7) / 8, TPB>>>(predw, predb, out);
}